// round 3
// baseline (speedup 1.0000x reference)
#include <cuda_runtime.h>
#include <cstdint>

// VectorQuantizer forward on GB300 (sm_103a).
// Distances emulate the reference's fp32 rounding lattice exactly:
//   d_k = fp32( fp32(||x||^2 - 2*dot) + ||w_k||^2 )
// with ||x||^2 and ||w_k||^2 as SEQUENTIAL square-then-add fp32 chains
// (matching XLA strict-order reduce), since one flipped argmin already
// exceeds the 1e-3 rel-err budget.

static constexpr int NTOK  = 131072;           // 32*64*64 tokens
static constexpr int DIM   = 64;
static constexpr int KC    = 512;              // codebook size
static constexpr int CHUNK = 128;              // codes per smem chunk (32 KB)
static constexpr int TPB   = 256;
static constexpr long long LELEM = (long long)NTOK * DIM;  // 8388608

__device__ int   g_idx[NTOK];
__device__ int   g_counts[KC];
__device__ float g_lossSum;

__device__ __forceinline__ unsigned long long pack2(float a, float b) {
    unsigned long long u;
    asm("mov.b64 %0, {%1, %2};" : "=l"(u) : "f"(a), "f"(b));
    return u;
}
__device__ __forceinline__ void unpack2(unsigned long long u, float& a, float& b) {
    asm("mov.b64 {%0, %1}, %2;" : "=f"(a), "=f"(b) : "l"(u));
}

__global__ void zero_kernel() {
    int t = threadIdx.x;
    if (t < KC) g_counts[t] = 0;
    if (t == 0) g_lossSum = 0.f;
}

// ---------------------------------------------------------------------------
// Kernel 2: per-token argmin over 512 codes on the reference fp32 lattice.
// One thread = one token. Token vector held as 32 packed f32x2 registers.
// Weight streamed through smem in 4 chunks of 128 codes.
// ---------------------------------------------------------------------------
__global__ void __launch_bounds__(TPB, 2) argmin_kernel(
        const float* __restrict__ in, const float* __restrict__ w) {
    __shared__ float wsh[CHUNK * DIM];
    __shared__ float c2sh[CHUNK];

    const int n = blockIdx.x * TPB + threadIdx.x;      // token id
    // NCHW gather: n = b*4096 + pos; x[d] = in[b*262144 + d*4096 + pos]
    const int base = (n >> 12) * (DIM * 4096) + (n & 4095);

    // Load token; compute A = ||x||^2 with sequential round(x*x) then round-add
    // (exactly XLA's mul-op followed by strict-order reduce; NO fma contraction).
    unsigned long long xv[DIM / 2];
    float A = 0.f;
#pragma unroll
    for (int i = 0; i < DIM / 2; i++) {
        float a = __ldg(in + base + (2 * i)     * 4096);
        float b = __ldg(in + base + (2 * i + 1) * 4096);
        A = __fadd_rn(A, __fmul_rn(a, a));
        A = __fadd_rn(A, __fmul_rn(b, b));
        xv[i] = pack2(a, b);
    }

    float best  = 3.402823466e+38f;
    int   bestk = 0;

#pragma unroll 1
    for (int c = 0; c < KC / CHUNK; c++) {
        __syncthreads();   // protect smem reuse across chunks
        // cooperative chunk load (float4, coalesced)
        const float4* wg  = reinterpret_cast<const float4*>(w) + c * (CHUNK * DIM / 4);
        float4*       ws4 = reinterpret_cast<float4*>(wsh);
#pragma unroll
        for (int i = 0; i < (CHUNK * DIM / 4) / TPB; i++)
            ws4[threadIdx.x + i * TPB] = wg[threadIdx.x + i * TPB];
        __syncthreads();
        // per-chunk code norms: sequential square-then-add, no contraction
        if (threadIdx.x < CHUNK) {
            float s = 0.f;
#pragma unroll
            for (int d = 0; d < DIM; d++) {
                float v = wsh[threadIdx.x * DIM + d];
                s = __fadd_rn(s, __fmul_rn(v, v));
            }
            c2sh[threadIdx.x] = s;
        }
        __syncthreads();

        const unsigned long long* w2 = reinterpret_cast<const unsigned long long*>(wsh);
#pragma unroll 8
        for (int k = 0; k < CHUNK; k++) {
            const unsigned long long* row = w2 + k * (DIM / 2);
            unsigned long long a0 = 0ull, a1 = 0ull;  // packed {0.f,0.f}
#pragma unroll
            for (int i = 0; i < DIM / 2; i += 2) {
                asm("fma.rn.f32x2 %0, %1, %2, %0;" : "+l"(a0) : "l"(xv[i]),     "l"(row[i]));
                asm("fma.rn.f32x2 %0, %1, %2, %0;" : "+l"(a1) : "l"(xv[i + 1]), "l"(row[i + 1]));
            }
            float s0, s1, s2, s3;
            unpack2(a0, s0, s1);
            unpack2(a1, s2, s3);
            float s = (s0 + s2) + (s1 + s3);       // dot (order-free, ~2e-9 noise)
            // reference lattice: round(A - 2*dot) then round(+ C)
            float T     = __fsub_rn(A, 2.0f * s);  // 2*s exact
            float score = __fadd_rn(T, c2sh[k]);
            if (score < best) { best = score; bestk = c * CHUNK + k; }
        }
    }

    g_idx[n] = bestk;
    atomicAdd(&g_counts[bestk], 1);
}

// ---------------------------------------------------------------------------
// Kernel 3: gather codebook rows to output (linear layout, per reference's
// no-inverse-permute reshape), straight-through value x + (q - x) in the
// reference's op order, and sum((q - x)^2) for the loss.
// ---------------------------------------------------------------------------
__global__ void __launch_bounds__(256) gather_kernel(
        const float* __restrict__ in, const float* __restrict__ w,
        float* __restrict__ out) {
    const int nvec = NTOK * (DIM / 4);   // float4 granularity: 2097152
    float acc = 0.f;
    for (int v = blockIdx.x * blockDim.x + threadIdx.x; v < nvec;
         v += gridDim.x * blockDim.x) {
        int tok = v >> 4;                // 16 float4 per token
        int idx = g_idx[tok];
        float4 wv = reinterpret_cast<const float4*>(w)[idx * (DIM / 4) + (v & 15)];
        float4 xv = reinterpret_cast<const float4*>(in)[v];
        float d0 = __fsub_rn(wv.x, xv.x), d1 = __fsub_rn(wv.y, xv.y);
        float d2 = __fsub_rn(wv.z, xv.z), d3 = __fsub_rn(wv.w, xv.w);
        float4 ov = make_float4(__fadd_rn(xv.x, d0), __fadd_rn(xv.y, d1),
                                __fadd_rn(xv.z, d2), __fadd_rn(xv.w, d3));
        reinterpret_cast<float4*>(out)[v] = ov;
        acc += d0 * d0 + d1 * d1 + d2 * d2 + d3 * d3;
    }
    // warp reduce then block reduce then one atomic
#pragma unroll
    for (int off = 16; off; off >>= 1)
        acc += __shfl_down_sync(0xffffffffu, acc, off);
    __shared__ float sh[8];
    if ((threadIdx.x & 31) == 0) sh[threadIdx.x >> 5] = acc;
    __syncthreads();
    if (threadIdx.x < 8) {
        float a = sh[threadIdx.x];
#pragma unroll
        for (int off = 4; off; off >>= 1)
            a += __shfl_down_sync(0x000000ffu, a, off);
        if (threadIdx.x == 0) atomicAdd(&g_lossSum, a);
    }
}

// ---------------------------------------------------------------------------
// Kernel 4: entropy over the 512-bin histogram -> perplexity; finalize loss.
// ---------------------------------------------------------------------------
__global__ void finalize_kernel(float* __restrict__ out, long long out_size) {
    __shared__ float sh[KC];
    int t = threadIdx.x;
    float p = (float)g_counts[t] / (float)NTOK;
    sh[t] = p * logf(p + 1e-10f);
    __syncthreads();
    for (int s = KC / 2; s; s >>= 1) {
        if (t < s) sh[t] += sh[t + s];
        __syncthreads();
    }
    if (t == 0) {
        if (out_size > LELEM) {
            float m = g_lossSum / (float)LELEM;       // /2^23, exact
            out[LELEM] = __fadd_rn(m, 0.25f * m);     // q_loss + 0.25*e_loss
        }
        if (out_size > LELEM + 1)
            out[LELEM + 1] = expf(-sh[0]);
    }
}

extern "C" void kernel_launch(void* const* d_in, const int* in_sizes, int n_in,
                              void* d_out, int out_size) {
    const float* in = (const float*)d_in[0];
    const float* w  = (const float*)d_in[1];
    float* out = (float*)d_out;

    zero_kernel<<<1, KC>>>();
    argmin_kernel<<<NTOK / TPB, TPB>>>(in, w);
    gather_kernel<<<1024, 256>>>(in, w, out);
    finalize_kernel<<<1, KC>>>(out, (long long)out_size);
}

// round 5
// speedup vs baseline: 1.0220x; 1.0220x over previous
#include <cuda_runtime.h>
#include <cstdint>

// VectorQuantizer forward on GB300 (sm_103a), round 4.
// Fast pass: continuous scores m_k = ||w_k||^2 - 2*dot (A drops out of argmin),
// 2 tokens/thread, LDS.128 code rows, best+second tracking.
// Tokens whose top-2 margin is within the fp32-lattice perturbation bound are
// re-resolved by an exact-lattice fallback (identical to the round-3 passing
// semantics: sequential ||x||^2 / ||w||^2, score = round(round(A-2s)+C),
// first-min index tie-break).

static constexpr int NTOK  = 131072;           // 32*64*64 tokens
static constexpr int DIM   = 64;
static constexpr int KC    = 512;              // codebook size
static constexpr int CHUNK = 128;              // codes per smem chunk (32 KB)
static constexpr long long LELEM = (long long)NTOK * DIM;  // 8388608

__device__ int   g_idx[NTOK];
__device__ int   g_counts[KC];
__device__ int   g_flag[NTOK];
__device__ int   g_nflag;
__device__ float g_lossSum;

__device__ __forceinline__ unsigned long long pack2(float a, float b) {
    unsigned long long u;
    asm("mov.b64 %0, {%1, %2};" : "=l"(u) : "f"(a), "f"(b));
    return u;
}
__device__ __forceinline__ void unpack2(unsigned long long u, float& a, float& b) {
    asm("mov.b64 {%0, %1}, %2;" : "=f"(a), "=f"(b) : "l"(u));
}
__device__ __forceinline__ void ffma2(unsigned long long& acc,
                                      unsigned long long x, unsigned long long w) {
    asm("fma.rn.f32x2 %0, %1, %2, %0;" : "+l"(acc) : "l"(x), "l"(w));
}

__global__ void zero_kernel() {
    int t = threadIdx.x;
    if (t < KC) g_counts[t] = 0;
    if (t == 0) { g_lossSum = 0.f; g_nflag = 0; }
}

// ---------------------------------------------------------------------------
// Fast argmin: 128 threads/block, 2 tokens/thread, 256 tokens/block.
// ---------------------------------------------------------------------------
__global__ void __launch_bounds__(128, 2) argmin_fast(
        const float* __restrict__ in, const float* __restrict__ w) {
    __shared__ float wsh[CHUNK * DIM];     // 32 KB
    __shared__ float c2sh[CHUNK];

    const int tid = threadIdx.x;
    const int t0  = blockIdx.x * 256 + tid;
    const int t1  = t0 + 128;
    const int baseA = (t0 >> 12) * (DIM * 4096) + (t0 & 4095);
    const int baseB = (t1 >> 12) * (DIM * 4096) + (t1 & 4095);

    unsigned long long xa[DIM / 2], xb[DIM / 2];
    float Aa = 0.f, Ab = 0.f;   // approx ||x||^2, only used for the margin threshold
#pragma unroll
    for (int i = 0; i < DIM / 2; i++) {
        float a0 = __ldg(in + baseA + (2 * i) * 4096);
        float a1 = __ldg(in + baseA + (2 * i + 1) * 4096);
        float b0 = __ldg(in + baseB + (2 * i) * 4096);
        float b1 = __ldg(in + baseB + (2 * i + 1) * 4096);
        Aa = fmaf(a0, a0, Aa); Aa = fmaf(a1, a1, Aa);
        Ab = fmaf(b0, b0, Ab); Ab = fmaf(b1, b1, Ab);
        xa[i] = pack2(a0, a1);
        xb[i] = pack2(b0, b1);
    }

    float bestA = 3.4e+38f, secA = 3.4e+38f;
    float bestB = 3.4e+38f, secB = 3.4e+38f;
    int   ka = 0, kb = 0;

#pragma unroll 1
    for (int c = 0; c < KC / CHUNK; c++) {
        __syncthreads();
        const float4* wg  = reinterpret_cast<const float4*>(w) + c * (CHUNK * DIM / 4);
        float4*       ws4 = reinterpret_cast<float4*>(wsh);
#pragma unroll
        for (int i = 0; i < (CHUNK * DIM / 4) / 128; i++)
            ws4[tid + i * 128] = wg[tid + i * 128];
        __syncthreads();
        {   // approx code norms (error absorbed by margin threshold)
            float s = 0.f;
#pragma unroll
            for (int d = 0; d < DIM; d++) {
                float v = wsh[tid * DIM + d];
                s = fmaf(v, v, s);
            }
            c2sh[tid] = s;
        }
        __syncthreads();

#pragma unroll 4
        for (int k = 0; k < CHUNK; k++) {
            const ulonglong2* row =
                reinterpret_cast<const ulonglong2*>(wsh + k * DIM);
            unsigned long long a0 = 0ull, a1 = 0ull, b0 = 0ull, b1 = 0ull;
#pragma unroll
            for (int i = 0; i < DIM / 4; i++) {
                ulonglong2 rr = row[i];               // LDS.128, broadcast
                ffma2(a0, xa[2 * i],     rr.x);
                ffma2(a1, xa[2 * i + 1], rr.y);
                ffma2(b0, xb[2 * i],     rr.x);
                ffma2(b1, xb[2 * i + 1], rr.y);
            }
            float p0, p1, p2, p3, q0, q1, q2, q3;
            unpack2(a0, p0, p1); unpack2(a1, p2, p3);
            unpack2(b0, q0, q1); unpack2(b1, q2, q3);
            float sa = (p0 + p2) + (p1 + p3);
            float sb = (q0 + q2) + (q1 + q3);
            float Cn = c2sh[k];
            float ma = fmaf(-2.f, sa, Cn);
            float mb = fmaf(-2.f, sb, Cn);
            int   kk = c * CHUNK + k;
            // best/second with first-min tie-break (ties leave ka and give margin 0)
            secA = fminf(secA, fmaxf(ma, bestA));
            if (ma < bestA) ka = kk;
            bestA = fminf(bestA, ma);
            secB = fminf(secB, fmaxf(mb, bestB));
            if (mb < bestB) kb = kk;
            bestB = fminf(bestB, mb);
        }
    }

    g_idx[t0] = ka;
    g_idx[t1] = kb;
    // margin threshold: max lattice perturbation of a score difference ~ 2*ulp(A)
    float thrA = fmaf(Aa, 2.4e-7f, 1e-6f);
    float thrB = fmaf(Ab, 2.4e-7f, 1e-6f);
    if (secA - bestA >= thrA) atomicAdd(&g_counts[ka], 1);
    else { int p = atomicAdd(&g_nflag, 1); g_flag[p] = t0; }
    if (secB - bestB >= thrB) atomicAdd(&g_counts[kb], 1);
    else { int p = atomicAdd(&g_nflag, 1); g_flag[p] = t1; }
}

// ---------------------------------------------------------------------------
// Exact-lattice fixup for ambiguous tokens. Warp-per-token; codes via smem.
// Reproduces round-3 semantics exactly.
// ---------------------------------------------------------------------------
__global__ void __launch_bounds__(128) fixup_kernel(
        const float* __restrict__ in, const float* __restrict__ w) {
    __shared__ float wsh[CHUNK * DIM];
    __shared__ float c2sh[CHUNK];
    const int tid = threadIdx.x;
    const int wid = tid >> 5, lid = tid & 31;
    const int nflag = g_nflag;

    for (int base = blockIdx.x * 4; base < nflag; base += gridDim.x * 4) {
        const int myTok = (base + wid < nflag) ? g_flag[base + wid] : -1;

        float A = 0.f;
        unsigned long long xv[DIM / 2];
        if (myTok >= 0) {
            int b = (myTok >> 12) * (DIM * 4096) + (myTok & 4095);
#pragma unroll
            for (int i = 0; i < DIM / 2; i++) {
                float a0 = __ldg(in + b + (2 * i) * 4096);
                float a1 = __ldg(in + b + (2 * i + 1) * 4096);
                A = __fadd_rn(A, __fmul_rn(a0, a0));
                A = __fadd_rn(A, __fmul_rn(a1, a1));
                xv[i] = pack2(a0, a1);
            }
        }

        float best = 3.4e+38f;
        int   bestk = 0;
#pragma unroll 1
        for (int c = 0; c < KC / CHUNK; c++) {
            __syncthreads();
            const float4* wg  = reinterpret_cast<const float4*>(w) + c * (CHUNK * DIM / 4);
            float4*       ws4 = reinterpret_cast<float4*>(wsh);
#pragma unroll
            for (int i = 0; i < (CHUNK * DIM / 4) / 128; i++)
                ws4[tid + i * 128] = wg[tid + i * 128];
            __syncthreads();
            {   // exact sequential code norms
                float s = 0.f;
#pragma unroll
                for (int d = 0; d < DIM; d++) {
                    float v = wsh[tid * DIM + d];
                    s = __fadd_rn(s, __fmul_rn(v, v));
                }
                c2sh[tid] = s;
            }
            __syncthreads();

            if (myTok >= 0) {
#pragma unroll
                for (int j = 0; j < 4; j++) {
                    int k = lid * 4 + j;   // ascending within lane & across lanes
                    const ulonglong2* row =
                        reinterpret_cast<const ulonglong2*>(wsh + k * DIM);
                    unsigned long long a0 = 0ull, a1 = 0ull;
#pragma unroll
                    for (int i = 0; i < DIM / 4; i++) {
                        ulonglong2 rr = row[i];
                        ffma2(a0, xv[2 * i],     rr.x);
                        ffma2(a1, xv[2 * i + 1], rr.y);
                    }
                    float p0, p1, p2, p3;
                    unpack2(a0, p0, p1); unpack2(a1, p2, p3);
                    float s  = (p0 + p2) + (p1 + p3);
                    float T  = __fsub_rn(A, 2.0f * s);
                    float sc = __fadd_rn(T, c2sh[k]);
                    if (sc < best) { best = sc; bestk = c * CHUNK + k; }
                }
            }
        }
        if (myTok >= 0) {
            // warp argmin with lowest-index tie-break
#pragma unroll
            for (int off = 16; off; off >>= 1) {
                float ob = __shfl_down_sync(0xffffffffu, best, off);
                int   ok = __shfl_down_sync(0xffffffffu, bestk, off);
                if (ob < best || (ob == best && ok < bestk)) { best = ob; bestk = ok; }
            }
            if (lid == 0) {
                g_idx[myTok] = bestk;
                atomicAdd(&g_counts[bestk], 1);
            }
        }
    }
}

// ---------------------------------------------------------------------------
// Gather + straight-through output + loss accumulation.
// ---------------------------------------------------------------------------
__global__ void __launch_bounds__(256) gather_kernel(
        const float* __restrict__ in, const float* __restrict__ w,
        float* __restrict__ out) {
    const int nvec = NTOK * (DIM / 4);   // 2097152 float4
    float acc = 0.f;
    for (int v = blockIdx.x * blockDim.x + threadIdx.x; v < nvec;
         v += gridDim.x * blockDim.x) {
        int tok = v >> 4;
        int idx = g_idx[tok];
        float4 wv = reinterpret_cast<const float4*>(w)[idx * (DIM / 4) + (v & 15)];
        float4 xv = reinterpret_cast<const float4*>(in)[v];
        float d0 = __fsub_rn(wv.x, xv.x), d1 = __fsub_rn(wv.y, xv.y);
        float d2 = __fsub_rn(wv.z, xv.z), d3 = __fsub_rn(wv.w, xv.w);
        float4 ov = make_float4(__fadd_rn(xv.x, d0), __fadd_rn(xv.y, d1),
                                __fadd_rn(xv.z, d2), __fadd_rn(xv.w, d3));
        reinterpret_cast<float4*>(out)[v] = ov;
        acc += d0 * d0 + d1 * d1 + d2 * d2 + d3 * d3;
    }
#pragma unroll
    for (int off = 16; off; off >>= 1)
        acc += __shfl_down_sync(0xffffffffu, acc, off);
    __shared__ float sh[8];
    if ((threadIdx.x & 31) == 0) sh[threadIdx.x >> 5] = acc;
    __syncthreads();
    if (threadIdx.x < 8) {
        float a = sh[threadIdx.x];
#pragma unroll
        for (int off = 4; off; off >>= 1)
            a += __shfl_down_sync(0x000000ffu, a, off);
        if (threadIdx.x == 0) atomicAdd(&g_lossSum, a);
    }
}

__global__ void finalize_kernel(float* __restrict__ out, long long out_size) {
    __shared__ float sh[KC];
    int t = threadIdx.x;
    float p = (float)g_counts[t] / (float)NTOK;
    sh[t] = p * logf(p + 1e-10f);
    __syncthreads();
    for (int s = KC / 2; s; s >>= 1) {
        if (t < s) sh[t] += sh[t + s];
        __syncthreads();
    }
    if (t == 0) {
        if (out_size > LELEM) {
            float m = g_lossSum / (float)LELEM;       // /2^23, exact
            out[LELEM] = __fadd_rn(m, 0.25f * m);
        }
        if (out_size > LELEM + 1)
            out[LELEM + 1] = expf(-sh[0]);
    }
}

extern "C" void kernel_launch(void* const* d_in, const int* in_sizes, int n_in,
                              void* d_out, int out_size) {
    const float* in = (const float*)d_in[0];
    const float* w  = (const float*)d_in[1];
    float* out = (float*)d_out;

    zero_kernel<<<1, KC>>>();
    argmin_fast<<<NTOK / 256, 128>>>(in, w);
    fixup_kernel<<<64, 128>>>(in, w);
    gather_kernel<<<1024, 256>>>(in, w, out);
    finalize_kernel<<<1, KC>>>(out, (long long)out_size);
}

// round 8
// speedup vs baseline: 1.3026x; 1.2745x over previous
#include <cuda_runtime.h>
#include <cuda_bf16.h>
#include <cstdint>

// VectorQuantizer forward on GB300 (sm_103 plain target), round 6:
// warp-level bf16 split mma.sync (fallback HMMA) argmin + exact-lattice fixup.

static constexpr int NTOK  = 131072;           // 32*64*64 tokens
static constexpr int DIM   = 64;
static constexpr int KC    = 512;              // codebook size
static constexpr int CHUNK = 128;              // fixup codes per smem chunk
static constexpr long long LELEM = (long long)NTOK * DIM;  // 8388608

// argmin geometry: 1024 CTAs x 256 threads, 128 tokens/CTA, 16 tokens/warp.
static constexpr int TPB   = 256;
static constexpr int NBLK  = NTOK / 128;       // 1024

// dynamic smem layout (bytes); all tiles use 128-B rows with XOR swizzle.
static constexpr int SM_BH = 0;                // 512 x 128B bf16-hi codes (64KB)
static constexpr int SM_BL = 65536;            // bf16-lo codes (64KB)
static constexpr int SM_AH = 131072;           // 128 x 128B bf16-hi tokens (16KB)
static constexpr int SM_AL = 147456;           // bf16-lo tokens (16KB)
static constexpr int SM_C2 = 163840;           // 512 fp32 code norms (2KB)
static constexpr int SM_A2 = 165888;           // 128 fp32 token norms (512B)
static constexpr int SM_TOTAL = 166400;

__device__ int   g_idx[NTOK];
__device__ int   g_counts[KC];
__device__ int   g_flag[NTOK];
__device__ int   g_nflag;
__device__ float g_lossSum;

__device__ __forceinline__ uint32_t smem_u32(const void* p) {
    uint32_t a;
    asm("{ .reg .u64 t; cvta.to.shared.u64 t, %1; cvt.u32.u64 %0, t; }"
        : "=r"(a) : "l"(p));
    return a;
}
__device__ __forceinline__ uint32_t bfpack(float a, float b) {
    uint32_t ua = (uint32_t)__bfloat16_as_ushort(__float2bfloat16(a));
    uint32_t ub = (uint32_t)__bfloat16_as_ushort(__float2bfloat16(b));
    return ua | (ub << 16);
}
__device__ __forceinline__ float bfres(float x) {   // x - bf16(x)
    return x - __bfloat162float(__float2bfloat16(x));
}
__device__ __forceinline__ unsigned long long pack2(float a, float b) {
    unsigned long long u;
    asm("mov.b64 %0, {%1, %2};" : "=l"(u) : "f"(a), "f"(b));
    return u;
}
__device__ __forceinline__ void unpack2(unsigned long long u, float& a, float& b) {
    asm("mov.b64 {%0, %1}, %2;" : "=f"(a), "=f"(b) : "l"(u));
}
__device__ __forceinline__ void ffma2(unsigned long long& acc,
                                      unsigned long long x, unsigned long long w) {
    asm("fma.rn.f32x2 %0, %1, %2, %0;" : "+l"(acc) : "l"(x), "l"(w));
}

#define LDSM4(r0, r1, r2, r3, addr)                                       \
    asm volatile("ldmatrix.sync.aligned.m8n8.x4.shared.b16 "              \
                 "{%0,%1,%2,%3}, [%4];"                                   \
                 : "=r"(r0), "=r"(r1), "=r"(r2), "=r"(r3) : "r"(addr))

#define MMA_BF16(c, a, b0v, b1v)                                          \
    asm volatile("mma.sync.aligned.m16n8k16.row.col.f32.bf16.bf16.f32 "   \
                 "{%0,%1,%2,%3}, {%4,%5,%6,%7}, {%8,%9}, {%0,%1,%2,%3};"  \
                 : "+f"((c)[0]), "+f"((c)[1]), "+f"((c)[2]), "+f"((c)[3]) \
                 : "r"((a)[0]), "r"((a)[1]), "r"((a)[2]), "r"((a)[3]),    \
                   "r"(b0v), "r"(b1v))

__global__ void zero_kernel() {
    int t = threadIdx.x;
    if (t < KC) g_counts[t] = 0;
    if (t == 0) { g_lossSum = 0.f; g_nflag = 0; }
}

// ---------------------------------------------------------------------------
// HMMA argmin.
// ---------------------------------------------------------------------------
__global__ void __launch_bounds__(TPB, 1) argmin_mma(
        const float* __restrict__ in, const float* __restrict__ w) {
    extern __shared__ char sm[];
    const uint32_t smb  = smem_u32(sm);
    const int tid  = threadIdx.x;
    const int lane = tid & 31;
    const int warp = tid >> 5;

    // ---- stage codebook: bf16 hi/lo swizzled + fp32 norms ----
#pragma unroll
    for (int rr = 0; rr < 2; rr++) {
        int r = tid + rr * TPB;                          // code row 0..511
        const float4* wr = reinterpret_cast<const float4*>(w) + r * 16;
        uint32_t swz = (uint32_t)((r & 7) << 4);
        char* bh = sm + SM_BH + r * 128;
        char* bl = sm + SM_BL + r * 128;
        float nrm = 0.f;
#pragma unroll
        for (int i = 0; i < 16; i++) {
            float4 v = wr[i];
            nrm = fmaf(v.x, v.x, nrm); nrm = fmaf(v.y, v.y, nrm);
            nrm = fmaf(v.z, v.z, nrm); nrm = fmaf(v.w, v.w, nrm);
            uint32_t o0 = (uint32_t)(8 * i)     ^ swz;
            uint32_t o1 = (uint32_t)(8 * i + 4) ^ swz;
            *(uint32_t*)(bh + o0) = bfpack(v.x, v.y);
            *(uint32_t*)(bh + o1) = bfpack(v.z, v.w);
            *(uint32_t*)(bl + o0) = bfpack(bfres(v.x), bfres(v.y));
            *(uint32_t*)(bl + o1) = bfpack(bfres(v.z), bfres(v.w));
        }
        *(float*)(sm + SM_C2 + r * 4) = nrm;
    }

    // ---- stage my CTA's 128 tokens (2 threads/token, 32 dims each) ----
    {
        int tok  = tid >> 1;                             // 0..127
        int half = tid & 1;
        int gtok = blockIdx.x * 128 + tok;
        int base = (gtok >> 12) * (DIM * 4096) + (gtok & 4095);
        uint32_t swz = (uint32_t)((tok & 7) << 4);
        char* ah = sm + SM_AH + tok * 128;
        char* al = sm + SM_AL + tok * 128;
        float A2 = 0.f;
#pragma unroll
        for (int i = 0; i < 16; i++) {
            int d = half * 32 + 2 * i;
            float a = __ldg(in + base + d * 4096);
            float b = __ldg(in + base + (d + 1) * 4096);
            A2 = fmaf(a, a, A2); A2 = fmaf(b, b, A2);
            uint32_t o = (uint32_t)(d * 2) ^ swz;
            *(uint32_t*)(ah + o) = bfpack(a, b);
            *(uint32_t*)(al + o) = bfpack(bfres(a), bfres(b));
        }
        A2 += __shfl_xor_sync(0xffffffffu, A2, 1);
        if (half == 0) *(float*)(sm + SM_A2 + tok * 4) = A2;
    }
    __syncthreads();

    // ---- A fragments for this warp's 16 tokens (hi + lo), k=0..63 ----
    uint32_t ah[16], al[16];
    {
        uint32_t aRow = (uint32_t)(warp * 16 + (lane & 15));
        uint32_t aSwz = (aRow & 7) << 4;
        uint32_t kbL  = (uint32_t)((lane >> 4) << 4);    // 0 or 16
        uint32_t baseH = smb + SM_AH + aRow * 128;
        uint32_t baseL = smb + SM_AL + aRow * 128;
#pragma unroll
        for (int ks = 0; ks < 4; ks++) {
            uint32_t off = (kbL + ks * 32) ^ aSwz;
            LDSM4(ah[ks*4], ah[ks*4+1], ah[ks*4+2], ah[ks*4+3], baseH + off);
            LDSM4(al[ks*4], al[ks*4+1], al[ks*4+2], al[ks*4+3], baseL + off);
        }
    }

    // ---- main loop: 64 n-tiles of 8 codes, 2 tiles in flight ----
    const float* c2 = (const float*)(sm + SM_C2);
    float best0 = 3.4e+38f, sec0 = 3.4e+38f;
    float best1 = 3.4e+38f, sec1 = 3.4e+38f;
    int   idx0 = 0, idx1 = 0;

    uint32_t bRowBase = (uint32_t)(lane & 7);
    uint32_t bSwz = (bRowBase & 7) << 4;
    uint32_t kb0  = (uint32_t)((lane >> 3) << 4);        // 0,16,32,48

#pragma unroll 1
    for (int nt = 0; nt < 64; nt += 2) {
        uint32_t rA = (uint32_t)(nt * 8) + bRowBase;
        uint32_t rB = rA + 8;
        uint32_t aHbA = smb + SM_BH + rA * 128, aLbA = smb + SM_BL + rA * 128;
        uint32_t aHbB = smb + SM_BH + rB * 128, aLbB = smb + SM_BL + rB * 128;
        uint32_t o0 = kb0 ^ bSwz, o1 = (kb0 + 64) ^ bSwz;

        uint32_t bhA[8], blA[8], bhB[8], blB[8];
        LDSM4(bhA[0], bhA[1], bhA[2], bhA[3], aHbA + o0);
        LDSM4(bhA[4], bhA[5], bhA[6], bhA[7], aHbA + o1);
        LDSM4(bhB[0], bhB[1], bhB[2], bhB[3], aHbB + o0);
        LDSM4(bhB[4], bhB[5], bhB[6], bhB[7], aHbB + o1);
        LDSM4(blA[0], blA[1], blA[2], blA[3], aLbA + o0);
        LDSM4(blA[4], blA[5], blA[6], blA[7], aLbA + o1);
        LDSM4(blB[0], blB[1], blB[2], blB[3], aLbB + o0);
        LDSM4(blB[4], blB[5], blB[6], blB[7], aLbB + o1);

        float cA[4] = {0.f, 0.f, 0.f, 0.f};
        float cB[4] = {0.f, 0.f, 0.f, 0.f};
#pragma unroll
        for (int ks = 0; ks < 4; ks++) {
            MMA_BF16(cA, &ah[ks*4], bhA[2*ks], bhA[2*ks+1]);
            MMA_BF16(cB, &ah[ks*4], bhB[2*ks], bhB[2*ks+1]);
        }
#pragma unroll
        for (int ks = 0; ks < 4; ks++) {
            MMA_BF16(cA, &ah[ks*4], blA[2*ks], blA[2*ks+1]);
            MMA_BF16(cB, &ah[ks*4], blB[2*ks], blB[2*ks+1]);
        }
#pragma unroll
        for (int ks = 0; ks < 4; ks++) {
            MMA_BF16(cA, &al[ks*4], bhA[2*ks], bhA[2*ks+1]);
            MMA_BF16(cB, &al[ks*4], bhB[2*ks], bhB[2*ks+1]);
        }

        // epilogue: C fragment layout — lane holds rows l/4, l/4+8;
        // cols (l%4)*2, +1 within the 8-col tile.
        int colA = nt * 8 + (lane & 3) * 2;
        float2 nA = *(const float2*)(c2 + colA);
        float2 nB = *(const float2*)(c2 + colA + 8);
        float m;
        m = fmaf(-2.f, cA[0], nA.x);
        if (m < best0) { sec0 = best0; best0 = m; idx0 = colA; }
        else sec0 = fminf(sec0, m);
        m = fmaf(-2.f, cA[1], nA.y);
        if (m < best0) { sec0 = best0; best0 = m; idx0 = colA + 1; }
        else sec0 = fminf(sec0, m);
        m = fmaf(-2.f, cA[2], nA.x);
        if (m < best1) { sec1 = best1; best1 = m; idx1 = colA; }
        else sec1 = fminf(sec1, m);
        m = fmaf(-2.f, cA[3], nA.y);
        if (m < best1) { sec1 = best1; best1 = m; idx1 = colA + 1; }
        else sec1 = fminf(sec1, m);

        m = fmaf(-2.f, cB[0], nB.x);
        if (m < best0) { sec0 = best0; best0 = m; idx0 = colA + 8; }
        else sec0 = fminf(sec0, m);
        m = fmaf(-2.f, cB[1], nB.y);
        if (m < best0) { sec0 = best0; best0 = m; idx0 = colA + 9; }
        else sec0 = fminf(sec0, m);
        m = fmaf(-2.f, cB[2], nB.x);
        if (m < best1) { sec1 = best1; best1 = m; idx1 = colA + 8; }
        else sec1 = fminf(sec1, m);
        m = fmaf(-2.f, cB[3], nB.y);
        if (m < best1) { sec1 = best1; best1 = m; idx1 = colA + 9; }
        else sec1 = fminf(sec1, m);
    }

    // ---- merge across the 4 lanes sharing each row ----
#pragma unroll
    for (int off = 1; off <= 2; off <<= 1) {
        float ob = __shfl_xor_sync(0xffffffffu, best0, off);
        float os = __shfl_xor_sync(0xffffffffu, sec0,  off);
        int   oi = __shfl_xor_sync(0xffffffffu, idx0,  off);
        float ns = fminf(fminf(sec0, os), fmaxf(best0, ob));
        if (ob < best0 || (ob == best0 && oi < idx0)) idx0 = oi;
        best0 = fminf(best0, ob);
        sec0  = ns;

        ob = __shfl_xor_sync(0xffffffffu, best1, off);
        os = __shfl_xor_sync(0xffffffffu, sec1,  off);
        oi = __shfl_xor_sync(0xffffffffu, idx1,  off);
        ns = fminf(fminf(sec1, os), fmaxf(best1, ob));
        if (ob < best1 || (ob == best1 && oi < idx1)) idx1 = oi;
        best1 = fminf(best1, ob);
        sec1  = ns;
    }

    if ((lane & 3) == 0) {
        int r  = warp * 16 + (lane >> 2);
        int t0 = blockIdx.x * 128 + r;
        int t1 = t0 + 8;
        float A20 = *(const float*)(sm + SM_A2 + r * 4);
        float A21 = *(const float*)(sm + SM_A2 + (r + 8) * 4);
        g_idx[t0] = idx0;
        g_idx[t1] = idx1;
        float thr0 = fmaf(A20, 2.4e-7f, 2.0e-5f);
        float thr1 = fmaf(A21, 2.4e-7f, 2.0e-5f);
        if (sec0 - best0 >= thr0) atomicAdd(&g_counts[idx0], 1);
        else { int p = atomicAdd(&g_nflag, 1); g_flag[p] = t0; }
        if (sec1 - best1 >= thr1) atomicAdd(&g_counts[idx1], 1);
        else { int p = atomicAdd(&g_nflag, 1); g_flag[p] = t1; }
    }
}

// ---------------------------------------------------------------------------
// Exact-lattice fixup for ambiguous tokens (round-3 passing semantics).
// ---------------------------------------------------------------------------
__global__ void __launch_bounds__(128) fixup_kernel(
        const float* __restrict__ in, const float* __restrict__ w) {
    __shared__ float wsh[CHUNK * DIM];
    __shared__ float c2sh[CHUNK];
    const int tid = threadIdx.x;
    const int wid = tid >> 5, lid = tid & 31;
    const int nflag = g_nflag;

    for (int base = blockIdx.x * 4; base < nflag; base += gridDim.x * 4) {
        const int myTok = (base + wid < nflag) ? g_flag[base + wid] : -1;

        float A = 0.f;
        unsigned long long xv[DIM / 2];
        if (myTok >= 0) {
            int b = (myTok >> 12) * (DIM * 4096) + (myTok & 4095);
#pragma unroll
            for (int i = 0; i < DIM / 2; i++) {
                float a0 = __ldg(in + b + (2 * i) * 4096);
                float a1 = __ldg(in + b + (2 * i + 1) * 4096);
                A = __fadd_rn(A, __fmul_rn(a0, a0));
                A = __fadd_rn(A, __fmul_rn(a1, a1));
                xv[i] = pack2(a0, a1);
            }
        }

        float best = 3.4e+38f;
        int   bestk = 0;
#pragma unroll 1
        for (int c = 0; c < KC / CHUNK; c++) {
            __syncthreads();
            const float4* wg  = reinterpret_cast<const float4*>(w) + c * (CHUNK * DIM / 4);
            float4*       ws4 = reinterpret_cast<float4*>(wsh);
#pragma unroll
            for (int i = 0; i < (CHUNK * DIM / 4) / 128; i++)
                ws4[tid + i * 128] = wg[tid + i * 128];
            __syncthreads();
            {
                float s = 0.f;
#pragma unroll
                for (int d = 0; d < DIM; d++) {
                    float v = wsh[tid * DIM + d];
                    s = __fadd_rn(s, __fmul_rn(v, v));
                }
                c2sh[tid] = s;
            }
            __syncthreads();

            if (myTok >= 0) {
#pragma unroll
                for (int j = 0; j < 4; j++) {
                    int k = lid * 4 + j;
                    const ulonglong2* row =
                        reinterpret_cast<const ulonglong2*>(wsh + k * DIM);
                    unsigned long long a0 = 0ull, a1 = 0ull;
#pragma unroll
                    for (int i = 0; i < DIM / 4; i++) {
                        ulonglong2 rr = row[i];
                        ffma2(a0, xv[2 * i],     rr.x);
                        ffma2(a1, xv[2 * i + 1], rr.y);
                    }
                    float p0, p1, p2, p3;
                    unpack2(a0, p0, p1); unpack2(a1, p2, p3);
                    float s  = (p0 + p2) + (p1 + p3);
                    float T  = __fsub_rn(A, 2.0f * s);
                    float sc = __fadd_rn(T, c2sh[k]);
                    if (sc < best) { best = sc; bestk = c * CHUNK + k; }
                }
            }
        }
        if (myTok >= 0) {
#pragma unroll
            for (int off = 16; off; off >>= 1) {
                float ob = __shfl_down_sync(0xffffffffu, best, off);
                int   ok = __shfl_down_sync(0xffffffffu, bestk, off);
                if (ob < best || (ob == best && ok < bestk)) { best = ob; bestk = ok; }
            }
            if (lid == 0) {
                g_idx[myTok] = bestk;
                atomicAdd(&g_counts[bestk], 1);
            }
        }
    }
}

// ---------------------------------------------------------------------------
// Gather + straight-through output + loss accumulation.
// ---------------------------------------------------------------------------
__global__ void __launch_bounds__(256) gather_kernel(
        const float* __restrict__ in, const float* __restrict__ w,
        float* __restrict__ out) {
    const int nvec = NTOK * (DIM / 4);
    float acc = 0.f;
    for (int v = blockIdx.x * blockDim.x + threadIdx.x; v < nvec;
         v += gridDim.x * blockDim.x) {
        int tok = v >> 4;
        int idx = g_idx[tok];
        float4 wv = reinterpret_cast<const float4*>(w)[idx * (DIM / 4) + (v & 15)];
        float4 xv = reinterpret_cast<const float4*>(in)[v];
        float d0 = __fsub_rn(wv.x, xv.x), d1 = __fsub_rn(wv.y, xv.y);
        float d2 = __fsub_rn(wv.z, xv.z), d3 = __fsub_rn(wv.w, xv.w);
        float4 ov = make_float4(__fadd_rn(xv.x, d0), __fadd_rn(xv.y, d1),
                                __fadd_rn(xv.z, d2), __fadd_rn(xv.w, d3));
        reinterpret_cast<float4*>(out)[v] = ov;
        acc += d0 * d0 + d1 * d1 + d2 * d2 + d3 * d3;
    }
#pragma unroll
    for (int off = 16; off; off >>= 1)
        acc += __shfl_down_sync(0xffffffffu, acc, off);
    __shared__ float sh[8];
    if ((threadIdx.x & 31) == 0) sh[threadIdx.x >> 5] = acc;
    __syncthreads();
    if (threadIdx.x < 8) {
        float a = sh[threadIdx.x];
#pragma unroll
        for (int off = 4; off; off >>= 1)
            a += __shfl_down_sync(0x000000ffu, a, off);
        if (threadIdx.x == 0) atomicAdd(&g_lossSum, a);
    }
}

__global__ void finalize_kernel(float* __restrict__ out, long long out_size) {
    __shared__ float sh[KC];
    int t = threadIdx.x;
    float p = (float)g_counts[t] / (float)NTOK;
    sh[t] = p * logf(p + 1e-10f);
    __syncthreads();
    for (int s = KC / 2; s; s >>= 1) {
        if (t < s) sh[t] += sh[t + s];
        __syncthreads();
    }
    if (t == 0) {
        if (out_size > LELEM) {
            float m = g_lossSum / (float)LELEM;
            out[LELEM] = __fadd_rn(m, 0.25f * m);
        }
        if (out_size > LELEM + 1)
            out[LELEM + 1] = expf(-sh[0]);
    }
}

extern "C" void kernel_launch(void* const* d_in, const int* in_sizes, int n_in,
                              void* d_out, int out_size) {
    const float* in = (const float*)d_in[0];
    const float* w  = (const float*)d_in[1];
    float* out = (float*)d_out;

    cudaFuncSetAttribute(argmin_mma,
                         cudaFuncAttributeMaxDynamicSharedMemorySize, SM_TOTAL);

    zero_kernel<<<1, KC>>>();
    argmin_mma<<<NBLK, TPB, SM_TOTAL>>>(in, w);
    fixup_kernel<<<64, 128>>>(in, w);
    gather_kernel<<<1024, 256>>>(in, w, out);
    finalize_kernel<<<1, KC>>>(out, (long long)out_size);
}

// round 9
// speedup vs baseline: 1.3144x; 1.0091x over previous
#include <cuda_runtime.h>
#include <cuda_bf16.h>
#include <cstdint>

// VectorQuantizer forward on GB300 (sm_103 plain target), round 9:
// bf16 split mma.sync argmin with 12 independent accumulator chains/warp,
// M=32 tokens/warp. Exact-lattice fixup for near-tie tokens.

static constexpr int NTOK  = 131072;           // 32*64*64 tokens
static constexpr int DIM   = 64;
static constexpr int KC    = 512;              // codebook size
static constexpr int CHUNK = 128;              // fixup codes per smem chunk
static constexpr long long LELEM = (long long)NTOK * DIM;  // 8388608

// argmin geometry: 512 CTAs x 256 threads, 256 tokens/CTA, 32 tokens/warp.
static constexpr int TPB   = 256;
static constexpr int TOKB  = 256;              // tokens per CTA
static constexpr int NBLK  = NTOK / TOKB;      // 512

// dynamic smem layout (bytes); 128-B rows with XOR swizzle.
static constexpr int SM_BH = 0;                // 512 x 128B bf16-hi codes (64KB)
static constexpr int SM_BL = 65536;            // bf16-lo codes (64KB)
static constexpr int SM_AH = 131072;           // 256 x 128B bf16-hi tokens (32KB)
static constexpr int SM_AL = 163840;           // bf16-lo tokens (32KB)
static constexpr int SM_C2 = 196608;           // 512 fp32 code norms (2KB)
static constexpr int SM_A2 = 198656;           // 256 fp32 token norms (1KB)
static constexpr int SM_TOTAL = 199680;

__device__ int   g_idx[NTOK];
__device__ int   g_counts[KC];
__device__ int   g_flag[NTOK];
__device__ int   g_nflag;
__device__ float g_lossSum;

__device__ __forceinline__ uint32_t smem_u32(const void* p) {
    uint32_t a;
    asm("{ .reg .u64 t; cvta.to.shared.u64 t, %1; cvt.u32.u64 %0, t; }"
        : "=r"(a) : "l"(p));
    return a;
}
__device__ __forceinline__ uint32_t bfpack(float a, float b) {
    uint32_t ua = (uint32_t)__bfloat16_as_ushort(__float2bfloat16(a));
    uint32_t ub = (uint32_t)__bfloat16_as_ushort(__float2bfloat16(b));
    return ua | (ub << 16);
}
__device__ __forceinline__ float bfres(float x) {   // x - bf16(x)
    return x - __bfloat162float(__float2bfloat16(x));
}
__device__ __forceinline__ unsigned long long pack2(float a, float b) {
    unsigned long long u;
    asm("mov.b64 %0, {%1, %2};" : "=l"(u) : "f"(a), "f"(b));
    return u;
}
__device__ __forceinline__ void unpack2(unsigned long long u, float& a, float& b) {
    asm("mov.b64 {%0, %1}, %2;" : "=f"(a), "=f"(b) : "l"(u));
}
__device__ __forceinline__ void ffma2(unsigned long long& acc,
                                      unsigned long long x, unsigned long long w) {
    asm("fma.rn.f32x2 %0, %1, %2, %0;" : "+l"(acc) : "l"(x), "l"(w));
}

#define LDSM4(r0, r1, r2, r3, addr)                                       \
    asm volatile("ldmatrix.sync.aligned.m8n8.x4.shared.b16 "              \
                 "{%0,%1,%2,%3}, [%4];"                                   \
                 : "=r"(r0), "=r"(r1), "=r"(r2), "=r"(r3) : "r"(addr))

#define MMA_BF16(c, a, b0v, b1v)                                          \
    asm volatile("mma.sync.aligned.m16n8k16.row.col.f32.bf16.bf16.f32 "   \
                 "{%0,%1,%2,%3}, {%4,%5,%6,%7}, {%8,%9}, {%0,%1,%2,%3};"  \
                 : "+f"((c)[0]), "+f"((c)[1]), "+f"((c)[2]), "+f"((c)[3]) \
                 : "r"((a)[0]), "r"((a)[1]), "r"((a)[2]), "r"((a)[3]),    \
                   "r"(b0v), "r"(b1v))

__device__ __forceinline__ void upd(float& best, float& sec, int& idx,
                                    float m, int col) {
    if (m < best) { sec = best; best = m; idx = col; }
    else sec = fminf(sec, m);
}

__global__ void zero_kernel() {
    int t = threadIdx.x;
    if (t < KC) g_counts[t] = 0;
    if (t == 0) { g_lossSum = 0.f; g_nflag = 0; }
}

// ---------------------------------------------------------------------------
// HMMA argmin, 12 independent accumulator chains per warp.
// ---------------------------------------------------------------------------
__global__ void __launch_bounds__(TPB, 1) argmin_mma(
        const float* __restrict__ in, const float* __restrict__ w) {
    extern __shared__ char sm[];
    const uint32_t smb  = smem_u32(sm);
    const int tid  = threadIdx.x;
    const int lane = tid & 31;
    const int warp = tid >> 5;

    // ---- stage codebook: bf16 hi/lo swizzled + fp32 norms (2 rows/thread) ----
#pragma unroll
    for (int rr = 0; rr < 2; rr++) {
        int r = tid + rr * TPB;                          // code row 0..511
        const float4* wr = reinterpret_cast<const float4*>(w) + r * 16;
        uint32_t swz = (uint32_t)((r & 7) << 4);
        char* bh = sm + SM_BH + r * 128;
        char* bl = sm + SM_BL + r * 128;
        float nrm = 0.f;
#pragma unroll
        for (int i = 0; i < 16; i++) {
            float4 v = wr[i];
            nrm = fmaf(v.x, v.x, nrm); nrm = fmaf(v.y, v.y, nrm);
            nrm = fmaf(v.z, v.z, nrm); nrm = fmaf(v.w, v.w, nrm);
            uint32_t o0 = (uint32_t)(8 * i)     ^ swz;
            uint32_t o1 = (uint32_t)(8 * i + 4) ^ swz;
            *(uint32_t*)(bh + o0) = bfpack(v.x, v.y);
            *(uint32_t*)(bh + o1) = bfpack(v.z, v.w);
            *(uint32_t*)(bl + o0) = bfpack(bfres(v.x), bfres(v.y));
            *(uint32_t*)(bl + o1) = bfpack(bfres(v.z), bfres(v.w));
        }
        *(float*)(sm + SM_C2 + r * 4) = nrm;
    }

    // ---- stage my CTA's 256 tokens (1 thread/token, all 64 dims) ----
    {
        int tok  = tid;                                  // 0..255
        int gtok = blockIdx.x * TOKB + tok;
        int base = (gtok >> 12) * (DIM * 4096) + (gtok & 4095);
        uint32_t swz = (uint32_t)((tok & 7) << 4);
        char* ah = sm + SM_AH + tok * 128;
        char* al = sm + SM_AL + tok * 128;
        float A2 = 0.f;
#pragma unroll
        for (int i = 0; i < 32; i++) {
            float a = __ldg(in + base + (2 * i)     * 4096);
            float b = __ldg(in + base + (2 * i + 1) * 4096);
            A2 = fmaf(a, a, A2); A2 = fmaf(b, b, A2);
            uint32_t o = (uint32_t)(4 * i) ^ swz;
            *(uint32_t*)(ah + o) = bfpack(a, b);
            *(uint32_t*)(al + o) = bfpack(bfres(a), bfres(b));
        }
        *(float*)(sm + SM_A2 + tok * 4) = A2;
    }
    __syncthreads();

    // ---- A fragments: this warp's 32 tokens = 2 m16 tiles, hi+lo, k=0..63 ----
    uint32_t ah[2][16], al[2][16];
#pragma unroll
    for (int mt = 0; mt < 2; mt++) {
        uint32_t aRow = (uint32_t)(warp * 32 + mt * 16 + (lane & 15));
        uint32_t aSwz = (aRow & 7) << 4;
        uint32_t kbL  = (uint32_t)((lane >> 4) << 4);    // 0 or 16 bytes
        uint32_t baseH = smb + SM_AH + aRow * 128;
        uint32_t baseL = smb + SM_AL + aRow * 128;
#pragma unroll
        for (int ks = 0; ks < 4; ks++) {
            uint32_t off = (kbL + ks * 32) ^ aSwz;
            LDSM4(ah[mt][ks*4], ah[mt][ks*4+1], ah[mt][ks*4+2], ah[mt][ks*4+3],
                  baseH + off);
            LDSM4(al[mt][ks*4], al[mt][ks*4+1], al[mt][ks*4+2], al[mt][ks*4+3],
                  baseL + off);
        }
    }

    // ---- main loop: 64 n-tiles of 8 codes, 2 tiles in flight ----
    const float* c2 = (const float*)(sm + SM_C2);
    float best[4], sec[4];
    int   idx[4];
#pragma unroll
    for (int s = 0; s < 4; s++) { best[s] = 3.4e+38f; sec[s] = 3.4e+38f; idx[s] = 0; }

    const uint32_t bRowBase = (uint32_t)(lane & 7);
    const uint32_t bSwz = bRowBase << 4;
    const uint32_t kb0  = (uint32_t)((lane >> 3) << 4);  // 0,16,32,48 bytes

#pragma unroll 1
    for (int nt = 0; nt < 64; nt += 2) {
        uint32_t rA = (uint32_t)(nt * 8) + bRowBase;
        uint32_t rB = rA + 8;
        uint32_t hA = smb + SM_BH + rA * 128, lA = smb + SM_BL + rA * 128;
        uint32_t hB = smb + SM_BH + rB * 128, lB = smb + SM_BL + rB * 128;
        uint32_t o0 = kb0 ^ bSwz, o1 = (kb0 + 64) ^ bSwz;

        uint32_t bhA[8], blA[8], bhB[8], blB[8];
        LDSM4(bhA[0], bhA[1], bhA[2], bhA[3], hA + o0);
        LDSM4(bhA[4], bhA[5], bhA[6], bhA[7], hA + o1);
        LDSM4(bhB[0], bhB[1], bhB[2], bhB[3], hB + o0);
        LDSM4(bhB[4], bhB[5], bhB[6], bhB[7], hB + o1);
        LDSM4(blA[0], blA[1], blA[2], blA[3], lA + o0);
        LDSM4(blA[4], blA[5], blA[6], blA[7], lA + o1);
        LDSM4(blB[0], blB[1], blB[2], blB[3], lB + o0);
        LDSM4(blB[4], blB[5], blB[6], blB[7], lB + o1);

        // 12 independent accumulator chains: [mTile][nTile][product]
        float c000[4]={0,0,0,0}, c001[4]={0,0,0,0}, c002[4]={0,0,0,0};
        float c010[4]={0,0,0,0}, c011[4]={0,0,0,0}, c012[4]={0,0,0,0};
        float c100[4]={0,0,0,0}, c101[4]={0,0,0,0}, c102[4]={0,0,0,0};
        float c110[4]={0,0,0,0}, c111[4]={0,0,0,0}, c112[4]={0,0,0,0};
#pragma unroll
        for (int ks = 0; ks < 4; ks++) {
            MMA_BF16(c000, &ah[0][ks*4], bhA[2*ks], bhA[2*ks+1]);
            MMA_BF16(c100, &ah[1][ks*4], bhA[2*ks], bhA[2*ks+1]);
            MMA_BF16(c010, &ah[0][ks*4], bhB[2*ks], bhB[2*ks+1]);
            MMA_BF16(c110, &ah[1][ks*4], bhB[2*ks], bhB[2*ks+1]);
            MMA_BF16(c001, &ah[0][ks*4], blA[2*ks], blA[2*ks+1]);
            MMA_BF16(c101, &ah[1][ks*4], blA[2*ks], blA[2*ks+1]);
            MMA_BF16(c011, &ah[0][ks*4], blB[2*ks], blB[2*ks+1]);
            MMA_BF16(c111, &ah[1][ks*4], blB[2*ks], blB[2*ks+1]);
            MMA_BF16(c002, &al[0][ks*4], bhA[2*ks], bhA[2*ks+1]);
            MMA_BF16(c102, &al[1][ks*4], bhA[2*ks], bhA[2*ks+1]);
            MMA_BF16(c012, &al[0][ks*4], bhB[2*ks], bhB[2*ks+1]);
            MMA_BF16(c112, &al[1][ks*4], bhB[2*ks], bhB[2*ks+1]);
        }

        // combine products, convert to scores, update best/second
        int colA = nt * 8 + (lane & 3) * 2;
        float2 nA = *(const float2*)(c2 + colA);
        float2 nB = *(const float2*)(c2 + colA + 8);
#pragma unroll
        for (int j = 0; j < 4; j++) {
            int slot0 = (j >> 1);          // m-tile 0: slots 0 (rows +0) / 1 (+8)
            int slot1 = 2 + (j >> 1);      // m-tile 1: slots 2 (+16) / 3 (+24)
            float nAv = (j & 1) ? nA.y : nA.x;
            float nBv = (j & 1) ? nB.y : nB.x;
            float vA0 = (c000[j] + c001[j]) + c002[j];
            float vB0 = (c010[j] + c011[j]) + c012[j];
            float vA1 = (c100[j] + c101[j]) + c102[j];
            float vB1 = (c110[j] + c111[j]) + c112[j];
            upd(best[slot0], sec[slot0], idx[slot0], fmaf(-2.f, vA0, nAv), colA + (j & 1));
            upd(best[slot0], sec[slot0], idx[slot0], fmaf(-2.f, vB0, nBv), colA + 8 + (j & 1));
            upd(best[slot1], sec[slot1], idx[slot1], fmaf(-2.f, vA1, nAv), colA + (j & 1));
            upd(best[slot1], sec[slot1], idx[slot1], fmaf(-2.f, vB1, nBv), colA + 8 + (j & 1));
        }
    }

    // ---- merge across the 4 lanes sharing each row ----
#pragma unroll
    for (int s = 0; s < 4; s++) {
#pragma unroll
        for (int off = 1; off <= 2; off <<= 1) {
            float ob = __shfl_xor_sync(0xffffffffu, best[s], off);
            float os = __shfl_xor_sync(0xffffffffu, sec[s],  off);
            int   oi = __shfl_xor_sync(0xffffffffu, idx[s],  off);
            float ns = fminf(fminf(sec[s], os), fmaxf(best[s], ob));
            if (ob < best[s] || (ob == best[s] && oi < idx[s])) idx[s] = oi;
            best[s] = fminf(best[s], ob);
            sec[s]  = ns;
        }
    }

    if ((lane & 3) == 0) {
#pragma unroll
        for (int s = 0; s < 4; s++) {
            int r  = warp * 32 + (lane >> 2) + s * 8;     // local token
            int t0 = blockIdx.x * TOKB + r;
            float A2 = *(const float*)(sm + SM_A2 + r * 4);
            g_idx[t0] = idx[s];
            float thr = fmaf(A2, 2.4e-7f, 2.0e-5f);
            if (sec[s] - best[s] >= thr) atomicAdd(&g_counts[idx[s]], 1);
            else { int p = atomicAdd(&g_nflag, 1); g_flag[p] = t0; }
        }
    }
}

// ---------------------------------------------------------------------------
// Exact-lattice fixup for ambiguous tokens (round-3 passing semantics).
// ---------------------------------------------------------------------------
__global__ void __launch_bounds__(128) fixup_kernel(
        const float* __restrict__ in, const float* __restrict__ w) {
    __shared__ float wsh[CHUNK * DIM];
    __shared__ float c2sh[CHUNK];
    const int tid = threadIdx.x;
    const int wid = tid >> 5, lid = tid & 31;
    const int nflag = g_nflag;

    for (int base = blockIdx.x * 4; base < nflag; base += gridDim.x * 4) {
        const int myTok = (base + wid < nflag) ? g_flag[base + wid] : -1;

        float A = 0.f;
        unsigned long long xv[DIM / 2];
        if (myTok >= 0) {
            int b = (myTok >> 12) * (DIM * 4096) + (myTok & 4095);
#pragma unroll
            for (int i = 0; i < DIM / 2; i++) {
                float a0 = __ldg(in + b + (2 * i) * 4096);
                float a1 = __ldg(in + b + (2 * i + 1) * 4096);
                A = __fadd_rn(A, __fmul_rn(a0, a0));
                A = __fadd_rn(A, __fmul_rn(a1, a1));
                xv[i] = pack2(a0, a1);
            }
        }

        float best = 3.4e+38f;
        int   bestk = 0;
#pragma unroll 1
        for (int c = 0; c < KC / CHUNK; c++) {
            __syncthreads();
            const float4* wg  = reinterpret_cast<const float4*>(w) + c * (CHUNK * DIM / 4);
            float4*       ws4 = reinterpret_cast<float4*>(wsh);
#pragma unroll
            for (int i = 0; i < (CHUNK * DIM / 4) / 128; i++)
                ws4[tid + i * 128] = wg[tid + i * 128];
            __syncthreads();
            {
                float s = 0.f;
#pragma unroll
                for (int d = 0; d < DIM; d++) {
                    float v = wsh[tid * DIM + d];
                    s = __fadd_rn(s, __fmul_rn(v, v));
                }
                c2sh[tid] = s;
            }
            __syncthreads();

            if (myTok >= 0) {
#pragma unroll
                for (int j = 0; j < 4; j++) {
                    int k = lid * 4 + j;
                    const ulonglong2* row =
                        reinterpret_cast<const ulonglong2*>(wsh + k * DIM);
                    unsigned long long a0 = 0ull, a1 = 0ull;
#pragma unroll
                    for (int i = 0; i < DIM / 4; i++) {
                        ulonglong2 rr = row[i];
                        ffma2(a0, xv[2 * i],     rr.x);
                        ffma2(a1, xv[2 * i + 1], rr.y);
                    }
                    float p0, p1, p2, p3;
                    unpack2(a0, p0, p1); unpack2(a1, p2, p3);
                    float s  = (p0 + p2) + (p1 + p3);
                    float T  = __fsub_rn(A, 2.0f * s);
                    float sc = __fadd_rn(T, c2sh[k]);
                    if (sc < best) { best = sc; bestk = c * CHUNK + k; }
                }
            }
        }
        if (myTok >= 0) {
#pragma unroll
            for (int off = 16; off; off >>= 1) {
                float ob = __shfl_down_sync(0xffffffffu, best, off);
                int   ok = __shfl_down_sync(0xffffffffu, bestk, off);
                if (ob < best || (ob == best && ok < bestk)) { best = ob; bestk = ok; }
            }
            if (lid == 0) {
                g_idx[myTok] = bestk;
                atomicAdd(&g_counts[bestk], 1);
            }
        }
    }
}

// ---------------------------------------------------------------------------
// Gather + straight-through output + loss accumulation.
// ---------------------------------------------------------------------------
__global__ void __launch_bounds__(256) gather_kernel(
        const float* __restrict__ in, const float* __restrict__ w,
        float* __restrict__ out) {
    const int nvec = NTOK * (DIM / 4);
    float acc = 0.f;
    for (int v = blockIdx.x * blockDim.x + threadIdx.x; v < nvec;
         v += gridDim.x * blockDim.x) {
        int tok = v >> 4;
        int idx = g_idx[tok];
        float4 wv = reinterpret_cast<const float4*>(w)[idx * (DIM / 4) + (v & 15)];
        float4 xv = reinterpret_cast<const float4*>(in)[v];
        float d0 = __fsub_rn(wv.x, xv.x), d1 = __fsub_rn(wv.y, xv.y);
        float d2 = __fsub_rn(wv.z, xv.z), d3 = __fsub_rn(wv.w, xv.w);
        float4 ov = make_float4(__fadd_rn(xv.x, d0), __fadd_rn(xv.y, d1),
                                __fadd_rn(xv.z, d2), __fadd_rn(xv.w, d3));
        reinterpret_cast<float4*>(out)[v] = ov;
        acc += d0 * d0 + d1 * d1 + d2 * d2 + d3 * d3;
    }
#pragma unroll
    for (int off = 16; off; off >>= 1)
        acc += __shfl_down_sync(0xffffffffu, acc, off);
    __shared__ float sh[8];
    if ((threadIdx.x & 31) == 0) sh[threadIdx.x >> 5] = acc;
    __syncthreads();
    if (threadIdx.x < 8) {
        float a = sh[threadIdx.x];
#pragma unroll
        for (int off = 4; off; off >>= 1)
            a += __shfl_down_sync(0x000000ffu, a, off);
        if (threadIdx.x == 0) atomicAdd(&g_lossSum, a);
    }
}

__global__ void finalize_kernel(float* __restrict__ out, long long out_size) {
    __shared__ float sh[KC];
    int t = threadIdx.x;
    float p = (float)g_counts[t] / (float)NTOK;
    sh[t] = p * logf(p + 1e-10f);
    __syncthreads();
    for (int s = KC / 2; s; s >>= 1) {
        if (t < s) sh[t] += sh[t + s];
        __syncthreads();
    }
    if (t == 0) {
        if (out_size > LELEM) {
            float m = g_lossSum / (float)LELEM;
            out[LELEM] = __fadd_rn(m, 0.25f * m);
        }
        if (out_size > LELEM + 1)
            out[LELEM + 1] = expf(-sh[0]);
    }
}

extern "C" void kernel_launch(void* const* d_in, const int* in_sizes, int n_in,
                              void* d_out, int out_size) {
    const float* in = (const float*)d_in[0];
    const float* w  = (const float*)d_in[1];
    float* out = (float*)d_out;

    cudaFuncSetAttribute(argmin_mma,
                         cudaFuncAttributeMaxDynamicSharedMemorySize, SM_TOTAL);

    zero_kernel<<<1, KC>>>();
    argmin_mma<<<NBLK, TPB, SM_TOTAL>>>(in, w);
    fixup_kernel<<<64, 128>>>(in, w);
    gather_kernel<<<1024, 256>>>(in, w, out);
    finalize_kernel<<<1, KC>>>(out, (long long)out_size);
}